// round 6
// baseline (speedup 1.0000x reference)
#include <cuda_runtime.h>
#include <math.h>

#define B 64
#define N 4096
#define D 256
#define TEMPERATURE 0.1f
#define EPS 1e-8f

#define NBLK 16
#define SAMPLES_PER_BLK 4

// Cross-block finish scratch (allocation-free: __device__ globals).
__device__ float g_scratch[NBLK];
__device__ unsigned int g_ticket = 0;

// 16 blocks x 128 threads (4 warps). Warp w of block blk handles sample
// blk*4 + w: gather 3 rows (D=256 fp32), 5 warp-shuffle reductions, loss.
// Block combines its 4 losses via shared (deterministic order), writes one
// partial to scratch, then an acq_rel ticket atomic. The 16th arriver reads
// the 16 partials (one L2 trip) and writes the mean — all fixed-order FP,
// bitwise deterministic across replays.
__global__ __launch_bounds__(128, 1)
void graph_contrastive_loss_kernel(const float* __restrict__ emb,
                                   const int* __restrict__ anchor_idx,
                                   const int* __restrict__ pos_idx,
                                   const int* __restrict__ neg_graph_idx,
                                   const int* __restrict__ neg_node_idx,
                                   float* __restrict__ out) {
    __shared__ float s_loss[SAMPLES_PER_BLK];

    const int tid  = threadIdx.x;
    const int wid  = tid >> 5;
    const int lane = tid & 31;
    const int b    = blockIdx.x * SAMPLES_PER_BLK + wid;   // sample 0..63

    // 4 independent uniform-address index loads -> one memory round-trip.
    const int ai  = anchor_idx[b];
    const int pi  = pos_idx[b];
    const int ngi = neg_graph_idx[b];
    const int nni = neg_node_idx[b];

    const float4* a_ptr = (const float4*)(emb + ((long long)b   * N + ai)  * D);
    const float4* p_ptr = (const float4*)(emb + ((long long)b   * N + pi)  * D);
    const float4* n_ptr = (const float4*)(emb + ((long long)ngi * N + nni) * D);

    // 6 independent float4 loads per lane (MLP=6) -> one round-trip.
    float4 a0 = a_ptr[lane * 2];
    float4 a1 = a_ptr[lane * 2 + 1];
    float4 p0 = p_ptr[lane * 2];
    float4 p1 = p_ptr[lane * 2 + 1];
    float4 n0 = n_ptr[lane * 2];
    float4 n1 = n_ptr[lane * 2 + 1];

    float dot_ap = a0.x*p0.x + a0.y*p0.y + a0.z*p0.z + a0.w*p0.w
                 + a1.x*p1.x + a1.y*p1.y + a1.z*p1.z + a1.w*p1.w;
    float dot_an = a0.x*n0.x + a0.y*n0.y + a0.z*n0.z + a0.w*n0.w
                 + a1.x*n1.x + a1.y*n1.y + a1.z*n1.z + a1.w*n1.w;
    float na2 = a0.x*a0.x + a0.y*a0.y + a0.z*a0.z + a0.w*a0.w
              + a1.x*a1.x + a1.y*a1.y + a1.z*a1.z + a1.w*a1.w;
    float np2 = p0.x*p0.x + p0.y*p0.y + p0.z*p0.z + p0.w*p0.w
              + p1.x*p1.x + p1.y*p1.y + p1.z*p1.z + p1.w*p1.w;
    float nn2 = n0.x*n0.x + n0.y*n0.y + n0.z*n0.z + n0.w*n0.w
              + n1.x*n1.x + n1.y*n1.y + n1.z*n1.z + n1.w*n1.w;

    #pragma unroll
    for (int off = 16; off > 0; off >>= 1) {
        dot_ap += __shfl_down_sync(0xFFFFFFFFu, dot_ap, off);
        dot_an += __shfl_down_sync(0xFFFFFFFFu, dot_an, off);
        na2    += __shfl_down_sync(0xFFFFFFFFu, na2,    off);
        np2    += __shfl_down_sync(0xFFFFFFFFu, np2,    off);
        nn2    += __shfl_down_sync(0xFFFFFFFFu, nn2,    off);
    }

    if (lane == 0) {
        float na = fmaxf(sqrtf(na2), EPS);
        float np = fmaxf(sqrtf(np2), EPS);
        float nn = fmaxf(sqrtf(nn2), EPS);
        float pos_sim = dot_ap / (na * np) * (1.0f / TEMPERATURE);
        float neg_sim = dot_an / (na * nn) * (1.0f / TEMPERATURE);
        float x = neg_sim - pos_sim;
        s_loss[wid] = (x > 0.0f) ? (x + log1pf(expf(-x))) : log1pf(expf(x));
    }
    __syncthreads();

    if (tid == 0) {
        // Fixed-order block partial (deterministic).
        float partial = (s_loss[0] + s_loss[1]) + (s_loss[2] + s_loss[3]);
        g_scratch[blockIdx.x] = partial;

        // acq_rel ticket: release publishes the scratch store, acquire orders
        // the last block's scratch reads. Replaces __threadfence + atomicAdd.
        unsigned int old;
        asm volatile("atom.acq_rel.gpu.global.add.u32 %0, [%1], %2;"
                     : "=r"(old)
                     : "l"(&g_ticket), "r"(1u)
                     : "memory");

        if (old == NBLK - 1) {
            // Last arriver: one batched L2 trip for 16 partials, fixed-order sum.
            float v0 = __ldcg(&g_scratch[0]);
            float v1 = __ldcg(&g_scratch[1]);
            float v2 = __ldcg(&g_scratch[2]);
            float v3 = __ldcg(&g_scratch[3]);
            float v4 = __ldcg(&g_scratch[4]);
            float v5 = __ldcg(&g_scratch[5]);
            float v6 = __ldcg(&g_scratch[6]);
            float v7 = __ldcg(&g_scratch[7]);
            float v8 = __ldcg(&g_scratch[8]);
            float v9 = __ldcg(&g_scratch[9]);
            float va = __ldcg(&g_scratch[10]);
            float vb = __ldcg(&g_scratch[11]);
            float vc = __ldcg(&g_scratch[12]);
            float vd = __ldcg(&g_scratch[13]);
            float ve = __ldcg(&g_scratch[14]);
            float vf = __ldcg(&g_scratch[15]);
            float s = ((v0 + v1) + (v2 + v3)) + ((v4 + v5) + (v6 + v7))
                    + ((v8 + v9) + (va + vb)) + ((vc + vd) + (ve + vf));
            out[0] = s * (1.0f / (float)B);
            g_ticket = 0;                      // reset for next graph replay
        }
    }
}

extern "C" void kernel_launch(void* const* d_in, const int* in_sizes, int n_in,
                              void* d_out, int out_size) {
    // Input order:
    //   0: node_embeddings  float32 [B, N, D]
    //   1: graph_labels     int32   [B]   (unused)
    //   2: anchor_idx       int32   [B]
    //   3: pos_idx          int32   [B]
    //   4: neg_graph_idx    int32   [B]
    //   5: neg_node_idx     int32   [B]
    const float* emb        = (const float*)d_in[0];
    const int*   anchor_idx = (const int*)d_in[2];
    const int*   pos_idx    = (const int*)d_in[3];
    const int*   neg_graph  = (const int*)d_in[4];
    const int*   neg_node   = (const int*)d_in[5];
    float* out = (float*)d_out;

    graph_contrastive_loss_kernel<<<NBLK, 128>>>(emb, anchor_idx, pos_idx,
                                                 neg_graph, neg_node, out);
}